// round 9
// baseline (speedup 1.0000x reference)
#include <cuda_runtime.h>
#include <cuda_fp16.h>

// Non-local means, 4 x 1 x 1024 x 1024 fp32.
// h = 7/255, template 7x7, search 21x21, reflect-101 padding.
//
// Two SMEM tiles indexed by unreflected global coords (halo 13):
//   Sf : fp32 reflect-padded values (for tail/epilogue exactness)
//   S2 : half2 pairs S2[j] = (half(x[j]), half(x[j+1])) -> one LDS.32 serves
//        TWO search offsets (dx, dx+1); diff pipeline runs in half2.
// Vertical 7-box: half2 register sliding window (ring of 7).
// Early rejection: non-negligible weight needs ALL 7 window lanes V <= TH.
// Ballot the per-8-row min, test for a 7-consecutive-bit run; no run ->
// every weight in the 8-row group (both dx) is < 2^-25 -> skip the
// shuffle/ex2/accumulate tail. Error bound 441 * 2^-25 ~ 1.3e-5.
//
// R8: 8-row screen groups (halve BSSY/BSYNC branch regions) + hoisted row
// base pointers so interior-row LDS use immediate offsets (kill per-row IMAD).

static constexpr int IMG_H = 1024;
static constexpr int IMG_W = 1024;
static constexpr int OUT_H = 32;
static constexpr int OUT_W = 104;          // 4 warps * 26
static constexpr int REG_H = OUT_H + 26;   // 58
static constexpr int REG_W = OUT_W + 26;   // 130
static constexpr int NTHREADS = 256;
static constexpr int TILE_N = REG_H * REG_W;            // 7540
static constexpr int SMEM_BYTES = TILE_N * 4 * 2;       // fp32 + half2 tiles

// dist/h^2 = S49 * 65025/2401 = K*S49 ; weight = 2^(-C2*S49), C2 = K*log2e
static constexpr float C2F = 39.07174f;
// skip-safe: s7raw > 25/C2 = 0.6399 -> w < 2^-25. Margin for half rounding.
static constexpr float THR = 0.66f;

__device__ __forceinline__ int refl(int g, int n) {
    g = (g < 0) ? -g : g;
    return (g >= n) ? (2 * n - 2 - g) : g;
}

__device__ __forceinline__ float ex2(float x) {
    float r;
    asm("ex2.approx.ftz.f32 %0, %1;" : "=f"(r) : "f"(x));
    return r;
}

// One dx-pair (dxe, dxe+1) at one dy.
// RB  : row reflection for edge row-strips.
// LAST: hi component (dx = dxe+1) is out of range; screen may include it
//       (conservative) but the tail must not accumulate it.
template <bool RB, bool LAST>
__device__ __forceinline__ void nlm_pair(
    const float* __restrict__ Sf, const __half2* __restrict__ S2,
    const __half2* __restrict__ Cc2,
    float (&wacc)[16], float (&vacc)[16],
    int rw0, int r0m13, int colB, int colS, int dy, int dxe)
{
    const int cb = colB + dxe;
    const __half2* B = S2 + (dy - r0m13) * REG_W + cb;
    // interior fast path: row j = rw0-3+m  ->  Bp[m * REG_W], m constant
    const __half2* Bp = B + (rw0 - 3) * REG_W;
    // tail base: row rw0+i at Fp[i * REG_W]
    const float* Fp = Sf + (rw0 + dy - r0m13) * REG_W + colS + dxe;
    const __half thr = __float2half(THR);

    __half2 d2[7];
    __half2 V2 = __float2half2_rn(0.0f);
    // warm-up rows j = rw0-3 .. rw0+2
    #pragma unroll
    for (int m = 0; m < 6; ++m) {
        __half2 bv;
        if (RB) bv = B[refl(rw0 - 3 + m, IMG_H) * REG_W];
        else    bv = Bp[m * REG_W];
        __half2 t = __hsub2(Cc2[m], bv);
        d2[m] = __hmul2(t, t);
        V2 = __hadd2(V2, d2[m]);
    }
    // 2 groups of 8 rows
    #pragma unroll
    for (int g = 0; g < 2; ++g) {
        __half2 Vq[8];
        #pragma unroll
        for (int s = 0; s < 8; ++s) {
            int i = 8 * g + s;
            __half2 bv;
            if (RB) bv = B[refl(rw0 + 3 + i, IMG_H) * REG_W];
            else    bv = Bp[(i + 6) * REG_W];
            __half2 t  = __hsub2(Cc2[i + 6], bv);
            __half2 dn = __hmul2(t, t);
            V2 = __hadd2(V2, dn);
            d2[(i + 6) % 7] = dn;
            Vq[s] = V2;
            V2 = __hsub2(V2, d2[i % 7]);
        }
        // screen: min over 16 values (8 rows x 2 dx)
        __half2 mn2 = __hmin2(__hmin2(__hmin2(Vq[0], Vq[1]), __hmin2(Vq[2], Vq[3])),
                              __hmin2(__hmin2(Vq[4], Vq[5]), __hmin2(Vq[6], Vq[7])));
        __half mn = __hmin(__low2half(mn2), __high2half(mn2));
        unsigned msk = __ballot_sync(0xffffffffu, __hle(mn, thr));
        unsigned r = msk & (msk >> 1);
        r &= (r >> 2);
        r &= (r >> 3);                 // 7-consecutive-lane run
        if (r) {
            const int i0 = 8 * g;
            #pragma unroll
            for (int s = 0; s < 8; ++s) {
                __half2 h = Vq[s];
                __half2 a = __hadd2(h, __shfl_down_sync(0xffffffffu, h, 1));
                __half2 b2 = __hadd2(a, __shfl_down_sync(0xffffffffu, a, 2));
                __half2 s7 = __hadd2(b2,
                             __hadd2(__shfl_down_sync(0xffffffffu, a, 4),
                                     __shfl_down_sync(0xffffffffu, h, 6)));
                int i = i0 + s;
                const float* Fr = Fp + i * REG_W;
                float wlo = ex2(-C2F * __low2float(s7));
                wacc[i] += wlo;
                vacc[i]  = fmaf(wlo, Fr[0], vacc[i]);
                if (!LAST) {
                    float whi = ex2(-C2F * __high2float(s7));
                    wacc[i] += whi;
                    vacc[i]  = fmaf(whi, Fr[1], vacc[i]);
                }
            }
        }
    }
}

template <bool RB>
__device__ __forceinline__ void nlm_accum(
    const float* __restrict__ Sf, const __half2* __restrict__ S2,
    const __half2* __restrict__ Cc2,
    float (&wacc)[16], float (&vacc)[16],
    int rw0, int r0m13, int colB, int colS)
{
    #pragma unroll 1
    for (int dy = -10; dy <= 10; ++dy) {
        #pragma unroll 1
        for (int p = 0; p < 10; ++p) {
            nlm_pair<RB, false>(Sf, S2, Cc2, wacc, vacc,
                                rw0, r0m13, colB, colS, dy, -10 + 2 * p);
        }
        nlm_pair<RB, true>(Sf, S2, Cc2, wacc, vacc,
                           rw0, r0m13, colB, colS, dy, 10);
    }
}

__global__ __launch_bounds__(NTHREADS, 2)
void nlm_kernel(const float* __restrict__ x, float* __restrict__ out) {
    extern __shared__ unsigned char smem_raw[];
    float* Sf = reinterpret_cast<float*>(smem_raw);
    __half2* S2 = reinterpret_cast<__half2*>(smem_raw + TILE_N * 4);

    const int b  = blockIdx.z;
    const int r0 = blockIdx.y * OUT_H;
    const int c0 = blockIdx.x * OUT_W;
    const int tid = threadIdx.x;

    // fp32 reflect-padded tile
    const float* xb = x + (size_t)b * (IMG_H * IMG_W);
    #pragma unroll 4
    for (int idx = tid; idx < TILE_N; idx += NTHREADS) {
        int i = idx / REG_W;
        int j = idx - i * REG_W;
        int gr = refl(r0 - 13 + i, IMG_H);
        int gc = refl(c0 - 13 + j, IMG_W);
        Sf[idx] = xb[gr * IMG_W + gc];
    }
    __syncthreads();

    // half2 pair tile: S2[j] = (half(Sf[j]), half(Sf[j+1]))
    #pragma unroll 4
    for (int idx = tid; idx < TILE_N; idx += NTHREADS) {
        int i = idx / REG_W;
        int j = idx - i * REG_W;
        int j1 = (j + 1 < REG_W) ? (j + 1) : j;
        S2[idx] = __floats2half2_rn(Sf[i * REG_W + j], Sf[i * REG_W + j1]);
    }
    __syncthreads();

    const int w = tid >> 5, l = tid & 31;
    const int wx = w & 3, wy = w >> 2;
    const int rw0 = r0 + wy * 16;
    const int c0w = c0 + wx * 26;
    const int u = c0w - 3 + l;
    const int qc = refl(u, IMG_W);
    const int r0m13 = r0 - 13;
    const int c0m13 = c0 - 13;
    const int colB = qc - c0m13;
    const int lclamp = (l < 26) ? l : 25;
    const int colS = (c0w + lclamp) - c0m13;

    // center-column cache as duplicated half2
    __half2 Cc2[22];
    #pragma unroll
    for (int m = 0; m < 22; ++m) {
        int qr = refl(rw0 - 3 + m, IMG_H);
        Cc2[m] = __float2half2_rn(Sf[(qr - r0m13) * REG_W + colB]);
    }

    float wacc[16], vacc[16];
    #pragma unroll
    for (int i = 0; i < 16; ++i) { wacc[i] = 0.0f; vacc[i] = 0.0f; }

    const bool rowRefl = (rw0 - 3 < 0) || (rw0 + 18 >= IMG_H);
    if (!rowRefl) {
        nlm_accum<false>(Sf, S2, Cc2, wacc, vacc, rw0, r0m13, colB, colS);
    } else {
        nlm_accum<true>(Sf, S2, Cc2, wacc, vacc, rw0, r0m13, colB, colS);
    }

    const int cout = c0w + l;
    if (l < 26 && cout < IMG_W) {
        float* ob = out + (size_t)b * (IMG_H * IMG_W);
        #pragma unroll
        for (int i = 0; i < 16; ++i) {
            float q = vacc[i] / wacc[i];
            q = fminf(fmaxf(q, 0.0f), 1.0f);
            ob[(rw0 + i) * IMG_W + cout] = q;
        }
    }
}

extern "C" void kernel_launch(void* const* d_in, const int* in_sizes, int n_in,
                              void* d_out, int out_size) {
    const float* x = (const float*)d_in[0];
    float* out = (float*)d_out;
    (void)in_sizes; (void)n_in; (void)out_size;

    cudaFuncSetAttribute(nlm_kernel,
                         cudaFuncAttributeMaxDynamicSharedMemorySize,
                         SMEM_BYTES);

    dim3 grid((IMG_W + OUT_W - 1) / OUT_W,   // 10
              IMG_H / OUT_H,                 // 32
              4);
    dim3 block(NTHREADS);
    nlm_kernel<<<grid, block, SMEM_BYTES>>>(x, out);
}

// round 10
// speedup vs baseline: 1.5414x; 1.5414x over previous
#include <cuda_runtime.h>
#include <cuda_fp16.h>

// Non-local means, 4 x 1 x 1024 x 1024 fp32.
// h = 7/255, template 7x7, search 21x21, reflect-101 padding.
//
// Two SMEM tiles indexed by unreflected global coords (halo 13):
//   Sf : fp32 reflect-padded values (tail/epilogue exactness)
//   S2 : half2 pairs S2[j] = (half(x[j]), half(x[j+1])) -> one LDS.32 serves
//        TWO search offsets (dx, dx+1); diff pipeline runs in half2.
// Vertical 7-box via PREFIX-SUM RING: P_m = sum_{rows<=m} diff^2 (one HFMA2
// per row), window V = P_m - P_{m-7} (one HSUB2, ring slot = SSA register).
// Early rejection (R7-proven 4-row quads): non-negligible weight needs ALL 7
// window lanes V <= TH; ballot per-quad min, test 7-consecutive-bit run; no
// run -> all weights in quad < 2^-25 -> skip shuffle/ex2/accumulate tail.
// Error bound 441 * 2^-25 ~ 1.3e-5 (reference fp32 exp underflows these to 0).

static constexpr int IMG_H = 1024;
static constexpr int IMG_W = 1024;
static constexpr int OUT_H = 32;
static constexpr int OUT_W = 104;          // 4 warps * 26
static constexpr int REG_H = OUT_H + 26;   // 58
static constexpr int REG_W = OUT_W + 26;   // 130
static constexpr int NTHREADS = 256;
static constexpr int TILE_N = REG_H * REG_W;            // 7540
static constexpr int SMEM_BYTES = TILE_N * 4 * 2;       // fp32 + half2 tiles

// dist/h^2 = S49 * 65025/2401 = K*S49 ; weight = 2^(-C2*S49), C2 = K*log2e
static constexpr float C2F = 39.07174f;
// skip-safe: s7raw > 25/C2 = 0.6399 -> w < 2^-25. Margin for half rounding.
static constexpr float THR = 0.66f;

__device__ __forceinline__ int refl(int g, int n) {
    g = (g < 0) ? -g : g;
    return (g >= n) ? (2 * n - 2 - g) : g;
}

__device__ __forceinline__ float ex2(float x) {
    float r;
    asm("ex2.approx.ftz.f32 %0, %1;" : "=f"(r) : "f"(x));
    return r;
}

// One dx-pair (dxe, dxe+1) at one dy.
// RB  : row reflection for edge row-strips.
// LAST: hi component (dx = dxe+1) is out of range; screen may include it
//       (conservative) but the tail must not accumulate it.
template <bool RB, bool LAST>
__device__ __forceinline__ void nlm_pair(
    const float* __restrict__ Sf, const __half2* __restrict__ S2,
    const __half2* __restrict__ Cc2,
    float (&wacc)[16], float (&vacc)[16],
    int rw0, int r0m13, int colB, int colS, int dy, int dxe)
{
    const int cb = colB + dxe;
    const __half2* B = S2 + (dy - r0m13) * REG_W + cb;
    // interior fast path: row rw0-3+m  ->  Bp[m * REG_W], m constant
    const __half2* Bp = B + (rw0 - 3) * REG_W;
    // tail base: row rw0+i at Fp[i * REG_W]
    const float* Fp = Sf + (rw0 + dy - r0m13) * REG_W + colS + dxe;
    const __half thr = __float2half(THR);

    // prefix-sum ring: at step m (row rw0-3+m), ring[m%7] holds P_{m-7}
    __half2 ring[7];
    __half2 P = __float2half2_rn(0.0f);
    ring[6] = P;                       // P_{-1} = 0, read at m = 6
    // warm-up m = 0..5
    #pragma unroll
    for (int m = 0; m < 6; ++m) {
        __half2 bv;
        if (RB) bv = B[refl(rw0 - 3 + m, IMG_H) * REG_W];
        else    bv = Bp[m * REG_W];
        __half2 t = __hsub2(Cc2[m], bv);
        P = __hfma2(t, t, P);
        ring[m] = P;
    }
    // 4 quads of 4 rows (m = 4q+6 .. 4q+9, output row i = m-6)
    #pragma unroll
    for (int g = 0; g < 4; ++g) {
        __half2 Vq[4];
        #pragma unroll
        for (int s = 0; s < 4; ++s) {
            const int m = 4 * g + 6 + s;
            __half2 bv;
            if (RB) bv = B[refl(rw0 - 3 + m, IMG_H) * REG_W];
            else    bv = Bp[m * REG_W];
            __half2 t = __hsub2(Cc2[m], bv);
            P = __hfma2(t, t, P);
            Vq[s] = __hsub2(P, ring[m % 7]);
            ring[m % 7] = P;
        }
        // screen: min over 8 values (4 rows x 2 dx)
        __half2 mn2 = __hmin2(__hmin2(Vq[0], Vq[1]), __hmin2(Vq[2], Vq[3]));
        __half mn = __hmin(__low2half(mn2), __high2half(mn2));
        unsigned msk = __ballot_sync(0xffffffffu, __hle(mn, thr));
        unsigned r = msk & (msk >> 1);
        r &= (r >> 2);
        r &= (r >> 3);                 // 7-consecutive-lane run
        if (r) {
            const int i0 = 4 * g;
            #pragma unroll
            for (int s = 0; s < 4; ++s) {
                __half2 h = Vq[s];
                __half2 a = __hadd2(h, __shfl_down_sync(0xffffffffu, h, 1));
                __half2 b2 = __hadd2(a, __shfl_down_sync(0xffffffffu, a, 2));
                __half2 s7 = __hadd2(b2,
                             __hadd2(__shfl_down_sync(0xffffffffu, a, 4),
                                     __shfl_down_sync(0xffffffffu, h, 6)));
                int i = i0 + s;
                const float* Fr = Fp + i * REG_W;
                float wlo = ex2(-C2F * __low2float(s7));
                wacc[i] += wlo;
                vacc[i]  = fmaf(wlo, Fr[0], vacc[i]);
                if (!LAST) {
                    float whi = ex2(-C2F * __high2float(s7));
                    wacc[i] += whi;
                    vacc[i]  = fmaf(whi, Fr[1], vacc[i]);
                }
            }
        }
    }
}

template <bool RB>
__device__ __forceinline__ void nlm_accum(
    const float* __restrict__ Sf, const __half2* __restrict__ S2,
    const __half2* __restrict__ Cc2,
    float (&wacc)[16], float (&vacc)[16],
    int rw0, int r0m13, int colB, int colS)
{
    #pragma unroll 1
    for (int dy = -10; dy <= 10; ++dy) {
        #pragma unroll 1
        for (int p = 0; p < 10; ++p) {
            nlm_pair<RB, false>(Sf, S2, Cc2, wacc, vacc,
                                rw0, r0m13, colB, colS, dy, -10 + 2 * p);
        }
        nlm_pair<RB, true>(Sf, S2, Cc2, wacc, vacc,
                           rw0, r0m13, colB, colS, dy, 10);
    }
}

__global__ __launch_bounds__(NTHREADS, 2)
void nlm_kernel(const float* __restrict__ x, float* __restrict__ out) {
    extern __shared__ unsigned char smem_raw[];
    float* Sf = reinterpret_cast<float*>(smem_raw);
    __half2* S2 = reinterpret_cast<__half2*>(smem_raw + TILE_N * 4);

    const int b  = blockIdx.z;
    const int r0 = blockIdx.y * OUT_H;
    const int c0 = blockIdx.x * OUT_W;
    const int tid = threadIdx.x;

    // fp32 reflect-padded tile
    const float* xb = x + (size_t)b * (IMG_H * IMG_W);
    #pragma unroll 4
    for (int idx = tid; idx < TILE_N; idx += NTHREADS) {
        int i = idx / REG_W;
        int j = idx - i * REG_W;
        int gr = refl(r0 - 13 + i, IMG_H);
        int gc = refl(c0 - 13 + j, IMG_W);
        Sf[idx] = xb[gr * IMG_W + gc];
    }
    __syncthreads();

    // half2 pair tile: S2[j] = (half(Sf[j]), half(Sf[j+1]))
    #pragma unroll 4
    for (int idx = tid; idx < TILE_N; idx += NTHREADS) {
        int i = idx / REG_W;
        int j = idx - i * REG_W;
        int j1 = (j + 1 < REG_W) ? (j + 1) : j;
        S2[idx] = __floats2half2_rn(Sf[i * REG_W + j], Sf[i * REG_W + j1]);
    }
    __syncthreads();

    const int w = tid >> 5, l = tid & 31;
    const int wx = w & 3, wy = w >> 2;
    const int rw0 = r0 + wy * 16;
    const int c0w = c0 + wx * 26;
    const int u = c0w - 3 + l;
    const int qc = refl(u, IMG_W);
    const int r0m13 = r0 - 13;
    const int c0m13 = c0 - 13;
    const int colB = qc - c0m13;
    const int lclamp = (l < 26) ? l : 25;
    const int colS = (c0w + lclamp) - c0m13;

    // center-column cache as duplicated half2
    __half2 Cc2[22];
    #pragma unroll
    for (int m = 0; m < 22; ++m) {
        int qr = refl(rw0 - 3 + m, IMG_H);
        Cc2[m] = __float2half2_rn(Sf[(qr - r0m13) * REG_W + colB]);
    }

    float wacc[16], vacc[16];
    #pragma unroll
    for (int i = 0; i < 16; ++i) { wacc[i] = 0.0f; vacc[i] = 0.0f; }

    const bool rowRefl = (rw0 - 3 < 0) || (rw0 + 18 >= IMG_H);
    if (!rowRefl) {
        nlm_accum<false>(Sf, S2, Cc2, wacc, vacc, rw0, r0m13, colB, colS);
    } else {
        nlm_accum<true>(Sf, S2, Cc2, wacc, vacc, rw0, r0m13, colB, colS);
    }

    const int cout = c0w + l;
    if (l < 26 && cout < IMG_W) {
        float* ob = out + (size_t)b * (IMG_H * IMG_W);
        #pragma unroll
        for (int i = 0; i < 16; ++i) {
            float q = vacc[i] / wacc[i];
            q = fminf(fmaxf(q, 0.0f), 1.0f);
            ob[(rw0 + i) * IMG_W + cout] = q;
        }
    }
}

extern "C" void kernel_launch(void* const* d_in, const int* in_sizes, int n_in,
                              void* d_out, int out_size) {
    const float* x = (const float*)d_in[0];
    float* out = (float*)d_out;
    (void)in_sizes; (void)n_in; (void)out_size;

    cudaFuncSetAttribute(nlm_kernel,
                         cudaFuncAttributeMaxDynamicSharedMemorySize,
                         SMEM_BYTES);

    dim3 grid((IMG_W + OUT_W - 1) / OUT_W,   // 10
              IMG_H / OUT_H,                 // 32
              4);
    dim3 block(NTHREADS);
    nlm_kernel<<<grid, block, SMEM_BYTES>>>(x, out);
}